// round 13
// baseline (speedup 1.0000x reference)
#include <cuda_runtime.h>
#include <cstdint>

// TPT-SVF IIR — two-phase exact-boundary scan.
// R13: K1 reverted to R10 (GROUP=256). K2 rewritten with f32x2 packed math:
// warp covers all 64 rows (thread owns rows lane & lane+32, states/inputs
// packed as pairs) -> ~35% fewer issue slots per output.

#define NSAMP   131072
#define BATCH   64
#define GROUP   256
#define WARM    96
#define K1TILE  32
#define K1TILES ((GROUP + WARM) / K1TILE)    // 11
#define NGROUPS (NSAMP / GROUP)              // 512
#define C2      32
#define NCH2    (NSAMP / C2)                 // 4096

typedef unsigned long long u64;

__device__ float2 g_states[NCH2 * BATCH];    // 2MB scratch

__device__ __forceinline__ uint32_t smem_u32(const void* p) {
    return (uint32_t)__cvta_generic_to_shared(p);
}

#define PACK2(d, lo, hi)   asm("mov.b64 %0, {%1,%2};" : "=l"(d) : "f"(lo), "f"(hi))
#define UNPACK2(lo, hi, s) asm("mov.b64 {%0,%1}, %2;" : "=f"(lo), "=f"(hi) : "l"(s))
#define FMA2(d, a, b, c)   asm("fma.rn.f32x2 %0, %1, %2, %3;" : "=l"(d) : "l"(a), "l"(b), "l"(c))
#define MUL2(d, a, b)      asm("mul.rn.f32x2 %0, %1, %2;" : "=l"(d) : "l"(a), "l"(b))

// ---- coefficient folding ----
struct Coef {
    float a00, a01, a10, a11, b0, b1;
    float q00, q01, q10, q11;                          // A^4
    float ab0, ab1, a2b0, a2b1, a3b0, a3b1;
    float e0, e1, ex, ea0, ea1, ea20, ea21, ea30, ea31;
    float eb, eab, ea2b;
};

__device__ __forceinline__ Coef fold(const float* gp, const float* twoRp,
                                     const float* mixp) {
    Coef k;
    const float g    = *gp;
    const float twoR = *twoRp;
    const float m0 = mixp[0], m1 = mixp[1], m2 = mixp[2];

    const float T   = 1.0f / (1.0f + g * (g + twoR));
    const float h00 = T,      h01 = -g * T;
    const float h10 = g * T,  h11 = (twoR * g + 1.0f) * T;
    const float gb0 = g * T,  gb1 = g * g * T;

    k.a00 = 2.0f * h00 - 1.0f; k.a01 = 2.0f * h01;
    k.a10 = 2.0f * h10;        k.a11 = 2.0f * h11 - 1.0f;
    k.b0  = 2.0f * gb0;        k.b1  = 2.0f * gb1;

    const float c0 = twoR * (m0 - m2);
    const float c1 = m1 - m2;
    const float cx = m2;
    k.e0 = c0 * h00 + c1 * h10;
    k.e1 = c0 * h01 + c1 * h11;
    k.ex = c0 * gb0 + c1 * gb1 + cx;

    k.ea0  = k.e0 * k.a00 + k.e1 * k.a10;     k.ea1  = k.e0 * k.a01 + k.e1 * k.a11;
    k.ea20 = k.ea0 * k.a00 + k.ea1 * k.a10;   k.ea21 = k.ea0 * k.a01 + k.ea1 * k.a11;
    k.ea30 = k.ea20 * k.a00 + k.ea21 * k.a10; k.ea31 = k.ea20 * k.a01 + k.ea21 * k.a11;

    k.eb   = k.e0 * k.b0 + k.e1 * k.b1;
    k.eab  = k.ea0 * k.b0 + k.ea1 * k.b1;
    k.ea2b = k.ea20 * k.b0 + k.ea21 * k.b1;

    k.ab0  = k.a00 * k.b0 + k.a01 * k.b1;     k.ab1  = k.a10 * k.b0 + k.a11 * k.b1;
    k.a2b0 = k.a00 * k.ab0 + k.a01 * k.ab1;   k.a2b1 = k.a10 * k.ab0 + k.a11 * k.ab1;
    k.a3b0 = k.a00 * k.a2b0 + k.a01 * k.a2b1; k.a3b1 = k.a10 * k.a2b0 + k.a11 * k.a2b1;

    const float p00 = k.a00 * k.a00 + k.a01 * k.a10, p01 = k.a00 * k.a01 + k.a01 * k.a11;
    const float p10 = k.a10 * k.a00 + k.a11 * k.a10, p11 = k.a10 * k.a01 + k.a11 * k.a11;
    k.q00 = p00 * p00 + p01 * p10; k.q01 = p00 * p01 + p01 * p11;
    k.q10 = p10 * p00 + p11 * p10; k.q11 = p10 * p01 + p11 * p11;
    return k;
}

// =================== K1: boundary-state walk (R10 config) ===================
__global__ __launch_bounds__(32, 16) void svf_states_kernel(
    const float* __restrict__ audio,
    const float* __restrict__ gp,
    const float* __restrict__ twoRp,
    const float* __restrict__ mixp)
{
    __shared__ float4 sm[3][32 * 8];          // 3 x 4KB

    const int lane  = threadIdx.x;
    const int group = blockIdx.x >> 1;
    const int rbase = (blockIdx.x & 1) * 32;
    const int base  = group * GROUP - WARM;

    const Coef K = fold(gp, twoRp, mixp);

    const uint32_t smemBase = smem_u32(&sm[0][0]);
    const uint32_t compBase = smemBase + ((uint32_t)lane << 7)
                            + (((uint32_t)lane & 7u) << 4);
    const uint32_t r0   = (uint32_t)(lane >> 3);
    const uint32_t cc   = (uint32_t)(lane & 7);
    const uint32_t stgA = smemBase + (r0 << 7) + ((cc ^ r0) << 4);
    const uint32_t stgB = stgA ^ 64u;
    const float* gsrc0 = audio + (size_t)(rbase + (int)r0) * NSAMP + 4 * (int)cc + base;

    auto stage = [&](int t, uint32_t bufOff) {
        if (base + t * K1TILE >= 0) {
            const float* src = gsrc0 + t * K1TILE;
            #pragma unroll
            for (int kk = 0; kk < 8; ++kk) {
                const uint32_t d = ((kk & 1) ? stgB : stgA) + bufOff + (uint32_t)(kk * 512);
                asm volatile("cp.async.cg.shared.global [%0], [%1], 16;\n"
                             :: "r"(d), "l"(src + (size_t)(4 * kk) * NSAMP));
            }
        }
        asm volatile("cp.async.commit_group;\n");
    };

    float s0 = 0.0f, s1 = 0.0f;

    auto walk_tile = [&](uint32_t bufOff, bool active) {
        if (active) {
            const uint32_t cb = compBase + bufOff;
            #pragma unroll
            for (int c = 0; c < 8; ++c) {
                float4 x;
                asm volatile("ld.shared.v4.f32 {%0,%1,%2,%3}, [%4];"
                             : "=f"(x.x), "=f"(x.y), "=f"(x.z), "=f"(x.w)
                             : "r"(cb ^ (uint32_t)(c << 4)));
                const float n0 = fmaf(K.q00, s0, fmaf(K.q01, s1,
                                 fmaf(K.a3b0, x.x, fmaf(K.a2b0, x.y,
                                 fmaf(K.ab0, x.z, K.b0 * x.w)))));
                const float n1 = fmaf(K.q10, s0, fmaf(K.q11, s1,
                                 fmaf(K.a3b1, x.x, fmaf(K.a2b1, x.y,
                                 fmaf(K.ab1, x.z, K.b1 * x.w)))));
                s0 = n0; s1 = n1;
            }
        }
    };

    stage(0, 0);
    stage(1, 4096);
    stage(2, 8192);

    const int cbase = group * (GROUP / C2);        // first 32-chunk index of group

    #pragma unroll
    for (int t = 0; t < K1TILES; ++t) {
        const uint32_t bufOff = (uint32_t)(t % 3) * 4096u;
        if (t >= 3)
            g_states[(size_t)(cbase + t - 3) * BATCH + rbase + lane] =
                make_float2(s0, s1);
        if (t + 3 < K1TILES) {
            asm volatile("cp.async.wait_group 2;\n" ::: "memory");
            __syncwarp();
            walk_tile(bufOff, base + t * K1TILE >= 0);
            stage(t + 3, bufOff);
        } else {
            if (t == K1TILES - 3)
                asm volatile("cp.async.wait_group 2;\n" ::: "memory");
            else if (t == K1TILES - 2)
                asm volatile("cp.async.wait_group 1;\n" ::: "memory");
            else
                asm volatile("cp.async.wait_group 0;\n" ::: "memory");
            __syncwarp();
            walk_tile(bufOff, base + t * K1TILE >= 0);
        }
    }
}

// =================== K2: per-chunk outputs, f32x2 packed ===================
// 4096 blocks x 32 thr: warp covers ALL 64 rows of one 32-sample chunk.
// Thread lane owns rows (lane, lane+32); states/inputs packed as f32x2 pairs.
__global__ __launch_bounds__(32, 20) void svf_out_kernel(
    const float* __restrict__ audio,
    const float* __restrict__ gp,
    const float* __restrict__ twoRp,
    const float* __restrict__ mixp,
    float* __restrict__ out)
{
    __shared__ float4 sm[2][32 * 8];           // half0 rows 0-31, half1 rows 32-63

    const int lane  = threadIdx.x;
    const int chunk = blockIdx.x;
    const int pos0  = chunk * C2;

    const uint32_t smemBase = smem_u32(&sm[0][0]);
    const uint32_t r0   = (uint32_t)(lane >> 3);
    const uint32_t cc   = (uint32_t)(lane & 7);
    const uint32_t stgA = smemBase + (r0 << 7) + ((cc ^ r0) << 4);
    const uint32_t stgB = stgA ^ 64u;

    // stage in: both halves, one commit group (16 cp.async of 16B)
    #pragma unroll
    for (int h = 0; h < 2; ++h) {
        const float* src = audio + (size_t)(h * 32 + (int)r0) * NSAMP + 4 * (int)cc + pos0;
        #pragma unroll
        for (int kk = 0; kk < 8; ++kk) {
            const uint32_t d = ((kk & 1) ? stgB : stgA)
                             + (uint32_t)(h * 4096) + (uint32_t)(kk * 512);
            asm volatile("cp.async.cg.shared.global [%0], [%1], 16;\n"
                         :: "r"(d), "l"(src + (size_t)(4 * kk) * NSAMP));
        }
    }
    asm volatile("cp.async.commit_group;\n");

    // states for both rows (coalesced float2 loads)
    const float2 sa = g_states[(size_t)chunk * BATCH + lane];
    const float2 sb = g_states[(size_t)chunk * BATCH + 32 + lane];

    const Coef K = fold(gp, twoRp, mixp);

    // pack broadcast coefficient pairs (once)
    u64 Q00, Q01, Q10, Q11, B0, B1, AB0, AB1, A2B0, A2B1, A3B0, A3B1;
    u64 E0, E1, EX, EA0, EA1, EA20, EA21, EA30, EA31, EB, EAB, EA2B;
    PACK2(Q00, K.q00, K.q00);   PACK2(Q01, K.q01, K.q01);
    PACK2(Q10, K.q10, K.q10);   PACK2(Q11, K.q11, K.q11);
    PACK2(B0, K.b0, K.b0);      PACK2(B1, K.b1, K.b1);
    PACK2(AB0, K.ab0, K.ab0);   PACK2(AB1, K.ab1, K.ab1);
    PACK2(A2B0, K.a2b0, K.a2b0); PACK2(A2B1, K.a2b1, K.a2b1);
    PACK2(A3B0, K.a3b0, K.a3b0); PACK2(A3B1, K.a3b1, K.a3b1);
    PACK2(E0, K.e0, K.e0);      PACK2(E1, K.e1, K.e1);   PACK2(EX, K.ex, K.ex);
    PACK2(EA0, K.ea0, K.ea0);   PACK2(EA1, K.ea1, K.ea1);
    PACK2(EA20, K.ea20, K.ea20); PACK2(EA21, K.ea21, K.ea21);
    PACK2(EA30, K.ea30, K.ea30); PACK2(EA31, K.ea31, K.ea31);
    PACK2(EB, K.eb, K.eb);      PACK2(EAB, K.eab, K.eab);  PACK2(EA2B, K.ea2b, K.ea2b);

    u64 S0, S1;
    PACK2(S0, sa.x, sb.x);
    PACK2(S1, sa.y, sb.y);

    const uint32_t compBase = smemBase + ((uint32_t)lane << 7)
                            + (((uint32_t)lane & 7u) << 4);

    asm volatile("cp.async.wait_group 0;\n" ::: "memory");
    __syncwarp();

    #pragma unroll
    for (int c = 0; c < 8; ++c) {
        const uint32_t a0 = compBase ^ (uint32_t)(c << 4);
        const uint32_t a1 = a0 + 4096u;
        float4 xa, xb;
        asm volatile("ld.shared.v4.f32 {%0,%1,%2,%3}, [%4];"
                     : "=f"(xa.x), "=f"(xa.y), "=f"(xa.z), "=f"(xa.w) : "r"(a0));
        asm volatile("ld.shared.v4.f32 {%0,%1,%2,%3}, [%4];"
                     : "=f"(xb.x), "=f"(xb.y), "=f"(xb.z), "=f"(xb.w) : "r"(a1));
        u64 X0, X1, X2, X3;
        PACK2(X0, xa.x, xb.x); PACK2(X1, xa.y, xb.y);
        PACK2(X2, xa.z, xb.z); PACK2(X3, xa.w, xb.w);

        u64 O0, O1, O2, O3, N0, N1, t0;
        // O0 = E0*S0 + E1*S1 + EX*X0
        MUL2(t0, EX, X0); FMA2(t0, E1, S1, t0); FMA2(O0, E0, S0, t0);
        // O1 = EA0*S0 + EA1*S1 + EB*X0 + EX*X1
        MUL2(t0, EX, X1); FMA2(t0, EB, X0, t0); FMA2(t0, EA1, S1, t0); FMA2(O1, EA0, S0, t0);
        // O2 = EA20*S0 + EA21*S1 + EAB*X0 + EB*X1 + EX*X2
        MUL2(t0, EX, X2); FMA2(t0, EB, X1, t0); FMA2(t0, EAB, X0, t0);
        FMA2(t0, EA21, S1, t0); FMA2(O2, EA20, S0, t0);
        // O3 = EA30*S0 + EA31*S1 + EA2B*X0 + EAB*X1 + EB*X2 + EX*X3
        MUL2(t0, EX, X3); FMA2(t0, EB, X2, t0); FMA2(t0, EAB, X1, t0);
        FMA2(t0, EA2B, X0, t0); FMA2(t0, EA31, S1, t0); FMA2(O3, EA30, S0, t0);
        // N0 = Q00*S0 + Q01*S1 + A3B0*X0 + A2B0*X1 + AB0*X2 + B0*X3
        MUL2(t0, B0, X3); FMA2(t0, AB0, X2, t0); FMA2(t0, A2B0, X1, t0);
        FMA2(t0, A3B0, X0, t0); FMA2(t0, Q01, S1, t0); FMA2(N0, Q00, S0, t0);
        // N1 = Q10*S0 + Q11*S1 + A3B1*X0 + A2B1*X1 + AB1*X2 + B1*X3
        MUL2(t0, B1, X3); FMA2(t0, AB1, X2, t0); FMA2(t0, A2B1, X1, t0);
        FMA2(t0, A3B1, X0, t0); FMA2(t0, Q11, S1, t0); FMA2(N1, Q10, S0, t0);
        S0 = N0; S1 = N1;

        float4 oa, ob;
        UNPACK2(oa.x, ob.x, O0); UNPACK2(oa.y, ob.y, O1);
        UNPACK2(oa.z, ob.z, O2); UNPACK2(oa.w, ob.w, O3);
        asm volatile("st.shared.v4.f32 [%0], {%1,%2,%3,%4};"
                     :: "r"(a0), "f"(oa.x), "f"(oa.y), "f"(oa.z), "f"(oa.w));
        asm volatile("st.shared.v4.f32 [%0], {%1,%2,%3,%4};"
                     :: "r"(a1), "f"(ob.x), "f"(ob.y), "f"(ob.z), "f"(ob.w));
    }
    __syncwarp();

    // stage out: both halves, coalesced STG.128
    #pragma unroll
    for (int h = 0; h < 2; ++h) {
        float* dst = out + (size_t)(h * 32 + (int)r0) * NSAMP + 4 * (int)cc + pos0;
        #pragma unroll
        for (int kk = 0; kk < 8; ++kk) {
            const uint32_t sa_ = ((kk & 1) ? stgB : stgA)
                               + (uint32_t)(h * 4096) + (uint32_t)(kk * 512);
            float4 v;
            asm volatile("ld.shared.v4.f32 {%0,%1,%2,%3}, [%4];"
                         : "=f"(v.x), "=f"(v.y), "=f"(v.z), "=f"(v.w) : "r"(sa_));
            *(float4*)(dst + (size_t)(4 * kk) * NSAMP) = v;
        }
    }
}

extern "C" void kernel_launch(void* const* d_in, const int* in_sizes, int n_in,
                              void* d_out, int out_size) {
    const float* audio = (const float*)d_in[0];
    const float* g     = (const float*)d_in[1];
    const float* twoR  = (const float*)d_in[2];
    const float* mix   = (const float*)d_in[3];
    float* outp        = (float*)d_out;

    static bool carveout_set = false;
    if (!carveout_set) {
        cudaFuncSetAttribute(svf_states_kernel, cudaFuncAttributePreferredSharedMemoryCarveout,
                             cudaSharedmemCarveoutMaxShared);
        cudaFuncSetAttribute(svf_out_kernel, cudaFuncAttributePreferredSharedMemoryCarveout,
                             cudaSharedmemCarveoutMaxShared);
        carveout_set = true;
    }

    svf_states_kernel<<<NGROUPS * 2, 32>>>(audio, g, twoR, mix);
    svf_out_kernel<<<NCH2, 32>>>(audio, g, twoR, mix, outp);
}